// round 8
// baseline (speedup 1.0000x reference)
#include <cuda_runtime.h>
#include <cuda_bf16.h>

#define NCAM 16

// Packed per-camera params (natural scalar layout, 16 floats/cam):
//   k 0..8: r00 r01 r02 r10 r11 r12 r20 r21 r22
//   k 9..11: t0 t1 t2   k 12,13: f0 f1   k 14,15: c0 c1
__device__ __align__(16) float g_params[NCAM * 16];

// ---------- f32x2 packed-math helpers (sm_103a) ----------
__device__ __forceinline__ unsigned long long pk2(float a, float b) {
    unsigned long long r;
    asm("mov.b64 %0, {%1, %2};" : "=l"(r) : "f"(a), "f"(b));
    return r;
}
__device__ __forceinline__ void upk2(unsigned long long v, float& a, float& b) {
    asm("mov.b64 {%0, %1}, %2;" : "=f"(a), "=f"(b) : "l"(v));
}
__device__ __forceinline__ unsigned long long fma2(unsigned long long a,
                                                   unsigned long long b,
                                                   unsigned long long c) {
    unsigned long long d;
    asm("fma.rn.f32x2 %0, %1, %2, %3;" : "=l"(d) : "l"(a), "l"(b), "l"(c));
    return d;
}
__device__ __forceinline__ unsigned long long mul2(unsigned long long a,
                                                   unsigned long long b) {
    unsigned long long d;
    asm("mul.rn.f32x2 %0, %1, %2;" : "=l"(d) : "l"(a), "l"(b));
    return d;
}
__device__ __forceinline__ float frcp(float x) {
    float r;
    asm("rcp.approx.f32 %0, %1;" : "=f"(r) : "f"(x));
    return r;
}

__global__ void prep_params_kernel(const float* __restrict__ R,
                                   const float* __restrict__ t,
                                   const float* __restrict__ f,
                                   const float* __restrict__ c)
{
    int s = threadIdx.x;
    if (s >= NCAM * 16) return;
    const int cam = s >> 4;
    const int k   = s & 15;
    float v;
    if (k < 9)       v = R[cam * 9 + k];
    else if (k < 12) v = t[cam * 3 + (k - 9)];
    else if (k < 14) v = f[cam * 2 + (k - 12)];
    else             v = c[cam * 2 + (k - 14)];
    g_params[s] = v;
}

// One camera per block (cam = blockIdx.x & 15), 8 points per thread.
// Camera-minor block ordering: all 16 camera-blocks of a point chunk run in
// the same wave, so each point chunk is DRAM-read once and L2-hit 15 times.
__global__ __launch_bounds__(256, 4)
void Projection_19713899889207_kernel(
    const float* __restrict__ pt3d,   // (3, Np) SoA
    float* __restrict__ out,          // (NC*Np, 2)
    int np)
{
    const int bid   = blockIdx.x;
    const int cam   = bid & (NCAM - 1);
    const int chunk = bid >> 4;

    const int base = chunk * 2048 + threadIdx.x * 8;   // first point (8/thread)
    if (base >= np) return;                            // np % 8 == 0

    // ---- camera params: 4 broadcast LDG.128, packed to f32x2 regs ONCE ----
    const float4* P4 = reinterpret_cast<const float4*>(g_params) + cam * 4;
    const float4 p0 = __ldg(P4 + 0);   // r00 r01 r02 r10
    const float4 p1 = __ldg(P4 + 1);   // r11 r12 r20 r21
    const float4 p2 = __ldg(P4 + 2);   // r22 t0  t1  t2
    const float4 p3 = __ldg(P4 + 3);   // f0  f1  c0  c1

    const unsigned long long R00 = pk2(p0.x, p0.x), R01 = pk2(p0.y, p0.y);
    const unsigned long long R02 = pk2(p0.z, p0.z), R10 = pk2(p0.w, p0.w);
    const unsigned long long R11 = pk2(p1.x, p1.x), R12 = pk2(p1.y, p1.y);
    const unsigned long long R20 = pk2(p1.z, p1.z), R21 = pk2(p1.w, p1.w);
    const unsigned long long R22 = pk2(p2.x, p2.x);
    const unsigned long long T0  = pk2(p2.y, p2.y), T1 = pk2(p2.z, p2.z);
    const unsigned long long T2  = pk2(p2.w, p2.w);
    const unsigned long long F0  = pk2(p3.x, p3.x), F1 = pk2(p3.y, p3.y);
    const unsigned long long C0  = pk2(p3.z, p3.z), C1 = pk2(p3.w, p3.w);

    const size_t npl = (size_t)np;
    // float4-granular plane pointers; q = index of first 4-point group
    const ulonglong2* xp = reinterpret_cast<const ulonglong2*>(pt3d);
    const ulonglong2* yp = reinterpret_cast<const ulonglong2*>(pt3d + npl);
    const ulonglong2* zp = reinterpret_cast<const ulonglong2*>(pt3d + 2 * npl);
    const size_t q = (size_t)base >> 2;

    float4* ob = reinterpret_cast<float4*>(out)
               + (size_t)cam * (npl >> 1) + ((size_t)base >> 1);

    #pragma unroll
    for (int h = 0; h < 2; ++h) {          // two groups of 4 points
        const ulonglong2 x = __ldg(xp + q + h);   // (x0,x1),(x2,x3)
        const ulonglong2 y = __ldg(yp + q + h);
        const ulonglong2 z = __ldg(zp + q + h);

        // pair A = points (0,1), pair B = points (2,3)
        const unsigned long long XA =
            fma2(R00, x.x, fma2(R01, y.x, fma2(R02, z.x, T0)));
        const unsigned long long XB =
            fma2(R00, x.y, fma2(R01, y.y, fma2(R02, z.y, T0)));
        const unsigned long long YA =
            fma2(R10, x.x, fma2(R11, y.x, fma2(R12, z.x, T1)));
        const unsigned long long YB =
            fma2(R10, x.y, fma2(R11, y.y, fma2(R12, z.y, T1)));
        const unsigned long long ZA =
            fma2(R20, x.x, fma2(R21, y.x, fma2(R22, z.x, T2)));
        const unsigned long long ZB =
            fma2(R20, x.y, fma2(R21, y.y, fma2(R22, z.y, T2)));

        float za0, za1, zb0, zb1;
        upk2(ZA, za0, za1);
        upk2(ZB, zb0, zb1);
        const unsigned long long IZA = pk2(frcp(za0), frcp(za1));
        const unsigned long long IZB = pk2(frcp(zb0), frcp(zb1));

        const unsigned long long UA = fma2(mul2(XA, IZA), F0, C0);
        const unsigned long long VA = fma2(mul2(YA, IZA), F1, C1);
        const unsigned long long UB = fma2(mul2(XB, IZB), F0, C0);
        const unsigned long long VB = fma2(mul2(YB, IZB), F1, C1);

        float ua0, ua1, va0, va1, ub0, ub1, vb0, vb1;
        upk2(UA, ua0, ua1);
        upk2(VA, va0, va1);
        upk2(UB, ub0, ub1);
        upk2(VB, vb0, vb1);

        // streaming stores: keep 256 MB of output from evicting point data in L2
        __stcs(ob + 2 * h,     make_float4(ua0, va0, ua1, va1));
        __stcs(ob + 2 * h + 1, make_float4(ub0, vb0, ub1, vb1));
    }
}

extern "C" void kernel_launch(void* const* d_in, const int* in_sizes, int n_in,
                              void* d_out, int out_size)
{
    // metadata order: pt3d (3,Np) f32, R (16,3,3) f32, t (16,3) f32,
    //                 f (16,2) f32, c (16,2) f32, mask (16,Np) i32 (unused)
    const float* pt3d = (const float*)d_in[0];
    const float* R    = (const float*)d_in[1];
    const float* t    = (const float*)d_in[2];
    const float* f    = (const float*)d_in[3];
    const float* c    = (const float*)d_in[4];
    float* out        = (float*)d_out;

    const int np = in_sizes[0] / 3;         // 2,000,000 (divisible by 8)

    prep_params_kernel<<<1, 256>>>(R, t, f, c);

    const int chunks = (np + 2047) / 2048;  // 2048 points per block
    const int blocks = chunks * NCAM;       // camera-minor ordering
    Projection_19713899889207_kernel<<<blocks, 256>>>(pt3d, out, np);
}

// round 9
// speedup vs baseline: 1.9043x; 1.9043x over previous
#include <cuda_runtime.h>
#include <cuda_bf16.h>

#define NCAM 16

// Per-camera smem layout (16 floats = 64B, four 16B groups):
//   grp0: r00 r10 r01 r11     (two column pairs)
//   grp1: r02 r12 t0  t1      (column pair + t pair)
//   grp2: f0  f1  c0  c1      (natural pairs)
//   grp3: r20 r21 r22 t2      (scalar row-3 for Z)
__device__ __align__(16) float g_params[NCAM * 16];

// ---------- f32x2 packed-math helpers (sm_103a) ----------
__device__ __forceinline__ unsigned long long pk2(float a, float b) {
    unsigned long long r;
    asm("mov.b64 %0, {%1, %2};" : "=l"(r) : "f"(a), "f"(b));
    return r;
}
__device__ __forceinline__ void upk2(unsigned long long v, float& a, float& b) {
    asm("mov.b64 {%0, %1}, %2;" : "=f"(a), "=f"(b) : "l"(v));
}
__device__ __forceinline__ unsigned long long fma2(unsigned long long a,
                                                   unsigned long long b,
                                                   unsigned long long c) {
    unsigned long long d;
    asm("fma.rn.f32x2 %0, %1, %2, %3;" : "=l"(d) : "l"(a), "l"(b), "l"(c));
    return d;
}
__device__ __forceinline__ unsigned long long mul2(unsigned long long a,
                                                   unsigned long long b) {
    unsigned long long d;
    asm("mul.rn.f32x2 %0, %1, %2;" : "=l"(d) : "l"(a), "l"(b));
    return d;
}
__device__ __forceinline__ float frcp(float x) {
    float r;
    asm("rcp.approx.f32 %0, %1;" : "=f"(r) : "f"(x));
    return r;
}
__device__ __forceinline__ void stcs_v2u64(void* p, unsigned long long a,
                                           unsigned long long b) {
    asm volatile("st.global.cs.v2.u64 [%0], {%1, %2};"
                 :: "l"(p), "l"(a), "l"(b) : "memory");
}

__global__ void prep_params_kernel(const float* __restrict__ R,
                                   const float* __restrict__ t,
                                   const float* __restrict__ f,
                                   const float* __restrict__ c)
{
    int s = threadIdx.x;
    if (s >= NCAM * 16) return;
    const int cam = s >> 4;
    const int k   = s & 15;
    const float* Rc = R + cam * 9;
    float v;
    switch (k) {
        case 0:  v = Rc[0]; break;  // r00
        case 1:  v = Rc[3]; break;  // r10
        case 2:  v = Rc[1]; break;  // r01
        case 3:  v = Rc[4]; break;  // r11
        case 4:  v = Rc[2]; break;  // r02
        case 5:  v = Rc[5]; break;  // r12
        case 6:  v = t[cam * 3 + 0]; break;
        case 7:  v = t[cam * 3 + 1]; break;
        case 8:  v = f[cam * 2 + 0]; break;
        case 9:  v = f[cam * 2 + 1]; break;
        case 10: v = c[cam * 2 + 0]; break;
        case 11: v = c[cam * 2 + 1]; break;
        case 12: v = Rc[6]; break;  // r20
        case 13: v = Rc[7]; break;  // r21
        case 14: v = Rc[8]; break;  // r22
        default: v = t[cam * 3 + 2]; break;  // t2
    }
    g_params[s] = v;
}

__global__ __launch_bounds__(256, 5)
void Projection_19713899889207_kernel(
    const float* __restrict__ pt3d,   // (3, Np) SoA
    float* __restrict__ out,          // (NC*Np, 2)
    int np)
{
    __shared__ __align__(16) float sp[NCAM * 16];
    const int tid = threadIdx.x;
    if (tid < NCAM * 16) sp[tid] = g_params[tid];
    __syncthreads();

    const int i = blockIdx.x * blockDim.x + tid;   // index of a PAIR of points
    const int np2 = np >> 1;
    if (i >= np2) return;

    // raw pair loads: u64 halves are (p0, p1)
    const unsigned long long x01 =
        __ldg(reinterpret_cast<const unsigned long long*>(pt3d) + i);
    const unsigned long long y01 =
        __ldg(reinterpret_cast<const unsigned long long*>(pt3d + (size_t)np) + i);
    const unsigned long long z01 =
        __ldg(reinterpret_cast<const unsigned long long*>(pt3d + 2 * (size_t)np) + i);

    // scalar coords (register-pair aliases, free) + camera-invariant dup packs
    float x0, x1, y0, y1, z0, z1;
    upk2(x01, x0, x1);
    upk2(y01, y0, y1);
    upk2(z01, z0, z1);
    const unsigned long long XX0 = pk2(x0, x0), XX1 = pk2(x1, x1);
    const unsigned long long YY0 = pk2(y0, y0), YY1 = pk2(y1, y1);
    const unsigned long long ZZ0 = pk2(z0, z0), ZZ1 = pk2(z1, z1);

    // output: one 16B store (2 points) per camera
    char* o = reinterpret_cast<char*>(out) + (size_t)i * 16;
    const size_t cam_stride = (size_t)np * 8;   // np points * 2 floats * 4B

    #pragma unroll 1
    for (int cam = 0; cam < NCAM; ++cam) {
        const ulonglong2* Q = reinterpret_cast<const ulonglong2*>(sp + cam * 16);
        const ulonglong2 qa = Q[0];   // ((r00,r10), (r01,r11))
        const ulonglong2 qb = Q[1];   // ((r02,r12), (t0,t1))
        const ulonglong2 qc = Q[2];   // ((f0,f1),   (c0,c1))
        const float4 r3 = reinterpret_cast<const float4*>(sp + cam * 16)[3];

        // depth (scalar): Z = r20*x + r21*y + r22*z + t2
        const float Za = fmaf(r3.x, x0, fmaf(r3.y, y0, fmaf(r3.z, z0, r3.w)));
        const float Zb = fmaf(r3.x, x1, fmaf(r3.y, y1, fmaf(r3.z, z1, r3.w)));
        const unsigned long long IZ0 = pk2(frcp(Za), frcp(Za));
        const unsigned long long IZ1 = pk2(frcp(Zb), frcp(Zb));

        // packed (X,Y) per point via column pairs
        const unsigned long long XY0 =
            fma2(qa.x, XX0, fma2(qa.y, YY0, fma2(qb.x, ZZ0, qb.y)));
        const unsigned long long XY1 =
            fma2(qa.x, XX1, fma2(qa.y, YY1, fma2(qb.x, ZZ1, qb.y)));

        // (u,v) = (X,Y)/Z * (f0,f1) + (c0,c1)  — already output layout
        const unsigned long long UV0 = fma2(mul2(XY0, IZ0), qc.x, qc.y);
        const unsigned long long UV1 = fma2(mul2(XY1, IZ1), qc.x, qc.y);

        stcs_v2u64(o, UV0, UV1);   // streaming STG.128: (u0,v0,u1,v1)
        o += cam_stride;
    }
}

extern "C" void kernel_launch(void* const* d_in, const int* in_sizes, int n_in,
                              void* d_out, int out_size)
{
    // metadata order: pt3d (3,Np) f32, R (16,3,3) f32, t (16,3) f32,
    //                 f (16,2) f32, c (16,2) f32, mask (16,Np) i32 (unused)
    const float* pt3d = (const float*)d_in[0];
    const float* R    = (const float*)d_in[1];
    const float* t    = (const float*)d_in[2];
    const float* f    = (const float*)d_in[3];
    const float* c    = (const float*)d_in[4];
    float* out        = (float*)d_out;

    const int np  = in_sizes[0] / 3;        // 2,000,000
    const int np2 = np / 2;

    prep_params_kernel<<<1, 256>>>(R, t, f, c);

    const int threads = 256;
    const int blocks  = (np2 + threads - 1) / threads;
    Projection_19713899889207_kernel<<<blocks, threads>>>(pt3d, out, np);
}